// round 6
// baseline (speedup 1.0000x reference)
#include <cuda_runtime.h>
#include <cuda_bf16.h>
#include <math.h>
#include <stdint.h>

// Problem constants
#define B_    64
#define S_    200
#define H_    16
#define DK_   64
#define DM_   1024
#define MROWS (B_ * S_)          // 12800
#define BH_   (B_ * H_)          // 1024
#define OUT_N  ((size_t)MROWS * DM_)       // 13107200
#define ATTN_N ((size_t)BH_ * S_ * S_)     // 40960000

// Scratch (allocation-free rule: __device__ globals)
__device__ __nv_bfloat16 g_xhi[MROWS * DM_];
__device__ __nv_bfloat16 g_xlo[MROWS * DM_];
__device__ __nv_bfloat16 g_whi[4][DM_ * DM_];
__device__ __nv_bfloat16 g_wlo[4][DM_ * DM_];
__device__ __nv_bfloat16 g_Qhi[BH_ * S_ * DK_];
__device__ __nv_bfloat16 g_Qlo[BH_ * S_ * DK_];
__device__ __nv_bfloat16 g_Khi[BH_ * S_ * DK_];
__device__ __nv_bfloat16 g_Klo[BH_ * S_ * DK_];
__device__ __nv_bfloat16 g_Vhi[BH_ * S_ * DK_];
__device__ __nv_bfloat16 g_Vlo[BH_ * S_ * DK_];
__device__ __nv_bfloat16 g_ctxhi[MROWS * DM_];
__device__ __nv_bfloat16 g_ctxlo[MROWS * DM_];
__device__ float g_attn_fb[BH_ * S_ * S_];
__device__ float g_out_fb[MROWS * DM_];

// ===========================================================================
// Helpers
// ===========================================================================
__device__ __forceinline__ uint32_t smem_to_u32(const void* p) {
    uint32_t a;
    asm("{ .reg .u64 t; cvta.to.shared.u64 t, %1; cvt.u32.u64 %0, t; }"
        : "=r"(a) : "l"(p));
    return a;
}

__device__ __forceinline__ void ldsm_x4(uint32_t& r0, uint32_t& r1,
                                        uint32_t& r2, uint32_t& r3, uint32_t addr) {
    asm volatile("ldmatrix.sync.aligned.m8n8.x4.shared.b16 {%0,%1,%2,%3}, [%4];"
                 : "=r"(r0), "=r"(r1), "=r"(r2), "=r"(r3) : "r"(addr));
}
__device__ __forceinline__ void ldsm_x4_t(uint32_t& r0, uint32_t& r1,
                                          uint32_t& r2, uint32_t& r3, uint32_t addr) {
    asm volatile("ldmatrix.sync.aligned.m8n8.x4.trans.shared.b16 {%0,%1,%2,%3}, [%4];"
                 : "=r"(r0), "=r"(r1), "=r"(r2), "=r"(r3) : "r"(addr));
}

__device__ __forceinline__ void mma_bf16(float* d, const uint32_t* a, const uint32_t* b) {
    asm volatile(
        "mma.sync.aligned.m16n8k16.row.col.f32.bf16.bf16.f32 "
        "{%0,%1,%2,%3}, {%4,%5,%6,%7}, {%8,%9}, {%0,%1,%2,%3};"
        : "+f"(d[0]), "+f"(d[1]), "+f"(d[2]), "+f"(d[3])
        : "r"(a[0]), "r"(a[1]), "r"(a[2]), "r"(a[3]), "r"(b[0]), "r"(b[1]));
}

#define STS128(addr, r0, r1, r2, r3) \
    asm volatile("st.shared.v4.b32 [%0], {%1,%2,%3,%4};" \
        :: "r"(addr), "r"(r0), "r"(r1), "r"(r2), "r"(r3) : "memory")

#define CP_ASYNC16(sm, gp) \
    asm volatile("{ .reg .u64 g; cvta.to.global.u64 g, %1; " \
                 "cp.async.cg.shared.global [%0], [g], 16; }" \
                 :: "r"(sm), "l"(gp) : "memory")
#define CP_COMMIT() asm volatile("cp.async.commit_group;" ::: "memory")
#define CP_WAIT0()  asm volatile("cp.async.wait_group 0;" ::: "memory")

// hi/lo bf16 split of a float pair, packed as 2x uint32 (bf16x2)
__device__ __forceinline__ void split2(float x, float y, uint32_t& hi, uint32_t& lo) {
    __nv_bfloat162 h = __floats2bfloat162_rn(x, y);
    float rx = x - __bfloat162float(h.x);
    float ry = y - __bfloat162float(h.y);
    __nv_bfloat162 l = __floats2bfloat162_rn(rx, ry);
    hi = *(uint32_t*)&h;
    lo = *(uint32_t*)&l;
}

// 64B-row swizzle (gemm): 4 chunks of 16B; chunk ^= (row>>1)&3
__device__ __forceinline__ uint32_t swz(int row, int chunk) {
    return (uint32_t)(row * 64 + ((chunk ^ ((row >> 1) & 3)) << 4));
}
// 128B-row swizzle (attention): 8 chunks of 16B; chunk ^= row&7
__device__ __forceinline__ uint32_t swz128(int row, int chunk) {
    return (uint32_t)(row * 128 + ((chunk ^ (row & 7)) << 4));
}

// ===========================================================================
// Split kernel: float -> bf16 hi/lo (vector of 8 per thread)
// ===========================================================================
__global__ void __launch_bounds__(256) split_kernel(
    const float* __restrict__ src, __nv_bfloat16* __restrict__ hi,
    __nv_bfloat16* __restrict__ lo, int n)
{
    int i = (blockIdx.x * 256 + threadIdx.x) * 8;
    if (i >= n) return;
    float4 v0 = *(const float4*)(src + i);
    float4 v1 = *(const float4*)(src + i + 4);
    uint32_t h[4], l[4];
    split2(v0.x, v0.y, h[0], l[0]); split2(v0.z, v0.w, h[1], l[1]);
    split2(v1.x, v1.y, h[2], l[2]); split2(v1.z, v1.w, h[3], l[3]);
    *(uint4*)(hi + i) = make_uint4(h[0], h[1], h[2], h[3]);
    *(uint4*)(lo + i) = make_uint4(l[0], l[1], l[2], l[3]);
}

// ===========================================================================
// bf16 hi/lo GEMM via mma.sync on pre-split inputs.
// C = A[M,1024] @ W^T[1024,1024] + bias. CTA 128x128, 8 warps, K-chunk 32,
// cp.async double buffer. OUT_MODE 0: bf16 hi/lo scatter to [b,h,s,dk].
// OUT_MODE 1: fp32 row-major.
// ===========================================================================
#define ST_AHI(s)  ((uint32_t)(s) * 32768u + 0u)
#define ST_ALO(s)  ((uint32_t)(s) * 32768u + 8192u)
#define ST_BHI(s)  ((uint32_t)(s) * 32768u + 16384u)
#define ST_BLO(s)  ((uint32_t)(s) * 32768u + 24576u)
#define GEMM_SMEM  65536

template <int OUT_MODE>
__global__ void __launch_bounds__(256, 1) gemm_mma(
    const __nv_bfloat16* __restrict__ Ahi, const __nv_bfloat16* __restrict__ Alo,
    const __nv_bfloat16* __restrict__ Whi, const __nv_bfloat16* __restrict__ Wlo,
    const float* __restrict__ bias,
    __nv_bfloat16* __restrict__ Chi, __nv_bfloat16* __restrict__ Clo,
    float* __restrict__ Cf)
{
    extern __shared__ char smem[];
    const uint32_t sb = smem_to_u32(smem);
    const int tid  = threadIdx.x;
    const int lane = tid & 31;
    const int wid  = tid >> 5;
    const int wm   = wid >> 2;
    const int wn   = wid & 3;
    const int m0   = blockIdx.y * 128;
    const int n0   = blockIdx.x * 128;

    float acc[4][4][4];
#pragma unroll
    for (int i = 0; i < 4; i++)
#pragma unroll
        for (int j = 0; j < 4; j++)
#pragma unroll
            for (int r = 0; r < 4; r++) acc[i][j][r] = 0.f;

    const int c0 = tid, c1 = tid + 256;
    const int r0c = c0 >> 2, cc0 = c0 & 3;
    const int r1c = c1 >> 2, cc1 = c1 & 3;
    const uint32_t sw0 = swz(r0c, cc0), sw1 = swz(r1c, cc1);

#define ISSUE_STAGE(st, kt_) do { \
    size_t ka = (size_t)(kt_) * 32; \
    const __nv_bfloat16* a0 = Ahi + (size_t)(m0 + r0c) * DM_ + ka + cc0 * 8; \
    const __nv_bfloat16* a1 = Ahi + (size_t)(m0 + r1c) * DM_ + ka + cc1 * 8; \
    CP_ASYNC16(sb + ST_AHI(st) + sw0, a0); \
    CP_ASYNC16(sb + ST_AHI(st) + sw1, a1); \
    a0 = Alo + (size_t)(m0 + r0c) * DM_ + ka + cc0 * 8; \
    a1 = Alo + (size_t)(m0 + r1c) * DM_ + ka + cc1 * 8; \
    CP_ASYNC16(sb + ST_ALO(st) + sw0, a0); \
    CP_ASYNC16(sb + ST_ALO(st) + sw1, a1); \
    a0 = Whi + (size_t)(n0 + r0c) * DM_ + ka + cc0 * 8; \
    a1 = Whi + (size_t)(n0 + r1c) * DM_ + ka + cc1 * 8; \
    CP_ASYNC16(sb + ST_BHI(st) + sw0, a0); \
    CP_ASYNC16(sb + ST_BHI(st) + sw1, a1); \
    a0 = Wlo + (size_t)(n0 + r0c) * DM_ + ka + cc0 * 8; \
    a1 = Wlo + (size_t)(n0 + r1c) * DM_ + ka + cc1 * 8; \
    CP_ASYNC16(sb + ST_BLO(st) + sw0, a0); \
    CP_ASYNC16(sb + ST_BLO(st) + sw1, a1); \
} while (0)

    ISSUE_STAGE(0, 0);
    CP_COMMIT();
    CP_WAIT0();
    __syncthreads();

    const int a_row_in = lane & 15;
    const int a_kh     = lane >> 4;
    const int b_col_in = (lane & 7) + ((lane >> 4) << 3);
    const int b_kh     = (lane >> 3) & 1;

    for (int kt = 0; kt < 32; kt++) {
        const int cur = kt & 1;

        if (kt < 31) {
            ISSUE_STAGE((kt + 1) & 1, kt + 1);
            CP_COMMIT();
        }

        const uint32_t ahiB = sb + ST_AHI(cur), aloB = sb + ST_ALO(cur);
        const uint32_t bhiB = sb + ST_BHI(cur), bloB = sb + ST_BLO(cur);

#pragma unroll
        for (int ks = 0; ks < 2; ks++) {
            uint32_t ahi[4][4], alo[4][4];
#pragma unroll
            for (int mf = 0; mf < 4; mf++) {
                int row = wm * 64 + mf * 16 + a_row_in;
                int ch  = ks * 2 + a_kh;
                uint32_t so = swz(row, ch);
                ldsm_x4(ahi[mf][0], ahi[mf][1], ahi[mf][2], ahi[mf][3], ahiB + so);
                ldsm_x4(alo[mf][0], alo[mf][1], alo[mf][2], alo[mf][3], aloB + so);
            }
            uint32_t bhi[4][2], blo[4][2];
#pragma unroll
            for (int bi = 0; bi < 2; bi++) {
                int col = wn * 32 + bi * 16 + b_col_in;
                int ch  = ks * 2 + b_kh;
                uint32_t so = swz(col, ch);
                uint32_t r0, r1, r2, r3;
                ldsm_x4(r0, r1, r2, r3, bhiB + so);
                bhi[bi * 2][0] = r0; bhi[bi * 2][1] = r1;
                bhi[bi * 2 + 1][0] = r2; bhi[bi * 2 + 1][1] = r3;
                ldsm_x4(r0, r1, r2, r3, bloB + so);
                blo[bi * 2][0] = r0; blo[bi * 2][1] = r1;
                blo[bi * 2 + 1][0] = r2; blo[bi * 2 + 1][1] = r3;
            }
#pragma unroll
            for (int mf = 0; mf < 4; mf++)
#pragma unroll
                for (int nf = 0; nf < 4; nf++) {
                    mma_bf16(acc[mf][nf], ahi[mf], bhi[nf]);
                    mma_bf16(acc[mf][nf], ahi[mf], blo[nf]);
                    mma_bf16(acc[mf][nf], alo[mf], bhi[nf]);
                }
        }
        if (kt < 31) {
            CP_WAIT0();
            __syncthreads();
        }
    }
#undef ISSUE_STAGE

    const int g  = lane >> 2;
    const int c2 = (lane & 3) * 2;
#pragma unroll
    for (int nf = 0; nf < 4; nf++) {
        const int n = n0 + wn * 32 + nf * 8 + c2;
        const float b0 = bias[n], b1 = bias[n + 1];
#pragma unroll
        for (int mf = 0; mf < 4; mf++) {
            const int m = m0 + wm * 64 + mf * 16 + g;
            if (OUT_MODE == 0) {
                int hh = n >> 6;
                int dk = n & 63;
                uint32_t hi0, lo0, hi1, lo1;
                split2(acc[mf][nf][0] + b0, acc[mf][nf][1] + b1, hi0, lo0);
                split2(acc[mf][nf][2] + b0, acc[mf][nf][3] + b1, hi1, lo1);
                int bb = m / S_;
                int ss = m - bb * S_;
                size_t off0 = (((size_t)bb * H_ + hh) * S_ + ss) * DK_ + dk;
                *(uint32_t*)(Chi + off0) = hi0;
                *(uint32_t*)(Clo + off0) = lo0;
                int m2 = m + 8;
                int bb2 = m2 / S_;
                int ss2 = m2 - bb2 * S_;
                size_t off1 = (((size_t)bb2 * H_ + hh) * S_ + ss2) * DK_ + dk;
                *(uint32_t*)(Chi + off1) = hi1;
                *(uint32_t*)(Clo + off1) = lo1;
            } else {
                float2 v0 = make_float2(acc[mf][nf][0] + b0, acc[mf][nf][1] + b1);
                float2 v1 = make_float2(acc[mf][nf][2] + b0, acc[mf][nf][3] + b1);
                *(float2*)(Cf + (size_t)m * DM_ + n)       = v0;
                *(float2*)(Cf + (size_t)(m + 8) * DM_ + n) = v1;
            }
        }
    }
}

// ===========================================================================
// Fused attention: CTA = (128 q-rows, bh). 256 threads / 8 warps.
// Q frags direct from gmem; K/V pre-split bf16 via cp.async (shared by all
// 8 warps). softmax in regs; attn->gmem fp32; ctx -> bf16 hi/lo scatter.
// ===========================================================================
#define FK_HI   0u
#define FK_LO   26624u
#define FV_HI   53248u
#define FV_LO   79872u
#define FA_SMEM 106496

__global__ void __launch_bounds__(256, 1) attn_fused(
    const int* __restrict__ mask, float* __restrict__ attn)
{
    extern __shared__ char smem[];
    const uint32_t sb = smem_to_u32(smem);
    const int tid  = threadIdx.x;
    const int lane = tid & 31;
    const int w    = tid >> 5;            // 0..7
    const int qt   = blockIdx.x;          // 0..1 (128-row q tiles)
    const int bh   = blockIdx.y;
    const int b    = bh >> 4;

    const __nv_bfloat16* Khi = g_Khi + (size_t)bh * S_ * DK_;
    const __nv_bfloat16* Klo = g_Klo + (size_t)bh * S_ * DK_;
    const __nv_bfloat16* Vhi = g_Vhi + (size_t)bh * S_ * DK_;
    const __nv_bfloat16* Vlo = g_Vlo + (size_t)bh * S_ * DK_;
    const __nv_bfloat16* Qhi = g_Qhi + (size_t)bh * S_ * DK_;
    const __nv_bfloat16* Qlo = g_Qlo + (size_t)bh * S_ * DK_;

    // ---- cp.async K/V hi/lo (200 rows x 8 chunks of 16B each) ----
    for (int c = tid; c < 1600; c += 256) {
        int r = c >> 3, cc = c & 7;
        uint32_t so = swz128(r, cc);
        size_t go = (size_t)r * DK_ + cc * 8;
        CP_ASYNC16(sb + FK_HI + so, Khi + go);
        CP_ASYNC16(sb + FK_LO + so, Klo + go);
        CP_ASYNC16(sb + FV_HI + so, Vhi + go);
        CP_ASYNC16(sb + FV_LO + so, Vlo + go);
    }
    CP_COMMIT();
    // zero-pad rows 200..207
    if (tid < 64) {
        int r = 200 + (tid >> 3), cc = tid & 7;
        uint32_t so = swz128(r, cc);
        STS128(sb + FK_HI + so, 0u, 0u, 0u, 0u);
        STS128(sb + FK_LO + so, 0u, 0u, 0u, 0u);
        STS128(sb + FV_HI + so, 0u, 0u, 0u, 0u);
        STS128(sb + FV_LO + so, 0u, 0u, 0u, 0u);
    }
    CP_WAIT0();
    __syncthreads();

    // ---- Scores ----
    float acc[25][4];
#pragma unroll
    for (int f = 0; f < 25; f++)
#pragma unroll
        for (int r = 0; r < 4; r++) acc[f][r] = 0.f;

    const int g  = lane >> 2;
    const int c2 = (lane & 3) * 2;
    const int b_col_in = (lane & 7) + ((lane >> 4) << 3);
    const int b_kh     = (lane >> 3) & 1;

    const int qr0 = qt * 128 + w * 16 + g;
    const int qr1 = qr0 + 8;
    const size_t qo0 = (size_t)min(qr0, S_ - 1) * DK_;
    const size_t qo1 = (size_t)min(qr1, S_ - 1) * DK_;

    for (int kb = 0; kb < 4; kb++) {
        const int col = kb * 16 + c2;
        uint32_t ahi[4], alo[4];
        ahi[0] = *(const uint32_t*)(Qhi + qo0 + col);
        ahi[1] = *(const uint32_t*)(Qhi + qo1 + col);
        ahi[2] = *(const uint32_t*)(Qhi + qo0 + col + 8);
        ahi[3] = *(const uint32_t*)(Qhi + qo1 + col + 8);
        alo[0] = *(const uint32_t*)(Qlo + qo0 + col);
        alo[1] = *(const uint32_t*)(Qlo + qo1 + col);
        alo[2] = *(const uint32_t*)(Qlo + qo0 + col + 8);
        alo[3] = *(const uint32_t*)(Qlo + qo1 + col + 8);
#pragma unroll
        for (int nb = 0; nb < 13; nb++) {
            int row = nb * 16 + b_col_in;
            int ch  = kb * 2 + b_kh;
            uint32_t so = swz128(row, ch);
            uint32_t h0, h1, h2, h3, l0, l1, l2, l3;
            ldsm_x4(h0, h1, h2, h3, sb + FK_HI + so);
            ldsm_x4(l0, l1, l2, l3, sb + FK_LO + so);
            uint32_t bh0[2] = {h0, h1}, bl0[2] = {l0, l1};
            mma_bf16(acc[nb * 2], ahi, bh0);
            mma_bf16(acc[nb * 2], ahi, bl0);
            mma_bf16(acc[nb * 2], alo, bh0);
            if (nb < 12) {
                uint32_t bh1[2] = {h2, h3}, bl1[2] = {l2, l3};
                mma_bf16(acc[nb * 2 + 1], ahi, bh1);
                mma_bf16(acc[nb * 2 + 1], ahi, bl1);
                mma_bf16(acc[nb * 2 + 1], alo, bh1);
            }
        }
    }

    // ---- scale + temporal bias + mask + softmax in registers ----
    const int gi0 = qr0;
    const int gi1 = qr1;
    const bool v0ok = (gi0 < S_);
    const bool v1ok = (gi1 < S_);
    const int* mrow0 = mask + (size_t)b * S_ * S_ + (size_t)gi0 * S_;
    const int* mrow1 = mask + (size_t)b * S_ * S_ + (size_t)gi1 * S_;
    const float BC = -0.1f / 200.0f;

    float mx0 = -1e30f, mx1 = -1e30f;
#pragma unroll
    for (int f = 0; f < 25; f++) {
        int gj = f * 8 + c2;
        int2 m0v = v0ok ? *(const int2*)(mrow0 + gj) : make_int2(1, 1);
        int2 m1v = v1ok ? *(const int2*)(mrow1 + gj) : make_int2(1, 1);
        float t00 = BC * fabsf((float)(gi0 - gj));
        float t01 = BC * fabsf((float)(gi0 - gj - 1));
        float t10 = BC * fabsf((float)(gi1 - gj));
        float t11 = BC * fabsf((float)(gi1 - gj - 1));
        acc[f][0] = (m0v.x == 0) ? -1e9f : fmaf(acc[f][0], 0.125f, t00);
        acc[f][1] = (m0v.y == 0) ? -1e9f : fmaf(acc[f][1], 0.125f, t01);
        acc[f][2] = (m1v.x == 0) ? -1e9f : fmaf(acc[f][2], 0.125f, t10);
        acc[f][3] = (m1v.y == 0) ? -1e9f : fmaf(acc[f][3], 0.125f, t11);
        mx0 = fmaxf(mx0, fmaxf(acc[f][0], acc[f][1]));
        mx1 = fmaxf(mx1, fmaxf(acc[f][2], acc[f][3]));
    }
    mx0 = fmaxf(mx0, __shfl_xor_sync(0xffffffffu, mx0, 1));
    mx0 = fmaxf(mx0, __shfl_xor_sync(0xffffffffu, mx0, 2));
    mx1 = fmaxf(mx1, __shfl_xor_sync(0xffffffffu, mx1, 1));
    mx1 = fmaxf(mx1, __shfl_xor_sync(0xffffffffu, mx1, 2));

    float s0 = 0.f, s1 = 0.f;
#pragma unroll
    for (int f = 0; f < 25; f++) {
        acc[f][0] = expf(acc[f][0] - mx0);
        acc[f][1] = expf(acc[f][1] - mx0);
        acc[f][2] = expf(acc[f][2] - mx1);
        acc[f][3] = expf(acc[f][3] - mx1);
        s0 += acc[f][0] + acc[f][1];
        s1 += acc[f][2] + acc[f][3];
    }
    s0 += __shfl_xor_sync(0xffffffffu, s0, 1);
    s0 += __shfl_xor_sync(0xffffffffu, s0, 2);
    s1 += __shfl_xor_sync(0xffffffffu, s1, 1);
    s1 += __shfl_xor_sync(0xffffffffu, s1, 2);
    const float i0 = 1.f / s0;
    const float i1 = 1.f / s1;

    float* arow0 = attn + (size_t)bh * S_ * S_ + (size_t)gi0 * S_;
    float* arow1 = attn + (size_t)bh * S_ * S_ + (size_t)gi1 * S_;
#pragma unroll
    for (int f = 0; f < 25; f++) {
        int gj = f * 8 + c2;
        acc[f][0] *= i0; acc[f][1] *= i0;
        acc[f][2] *= i1; acc[f][3] *= i1;
        if (v0ok) *(float2*)(arow0 + gj) = make_float2(acc[f][0], acc[f][1]);
        if (v1ok) *(float2*)(arow1 + gj) = make_float2(acc[f][2], acc[f][3]);
    }

    // ---- ctx = attn @ V ----
    float cacc[8][4];
#pragma unroll
    for (int nf = 0; nf < 8; nf++)
#pragma unroll
        for (int r = 0; r < 4; r++) cacc[nf][r] = 0.f;

#pragma unroll
    for (int kf = 0; kf < 13; kf++) {
        uint32_t ahi[4], alo[4];
        split2(acc[2 * kf][0], acc[2 * kf][1], ahi[0], alo[0]);
        split2(acc[2 * kf][2], acc[2 * kf][3], ahi[1], alo[1]);
        if (kf < 12) {
            split2(acc[2 * kf + 1][0], acc[2 * kf + 1][1], ahi[2], alo[2]);
            split2(acc[2 * kf + 1][2], acc[2 * kf + 1][3], ahi[3], alo[3]);
        } else {
            ahi[2] = alo[2] = ahi[3] = alo[3] = 0u;
        }
#pragma unroll
        for (int nb = 0; nb < 4; nb++) {
            int row = kf * 16 + (lane & 15);
            int ch  = nb * 2 + (lane >> 4);
            uint32_t so = swz128(row, ch);
            uint32_t h0, h1, h2, h3, l0, l1, l2, l3;
            ldsm_x4_t(h0, h1, h2, h3, sb + FV_HI + so);
            ldsm_x4_t(l0, l1, l2, l3, sb + FV_LO + so);
            uint32_t bh0[2] = {h0, h1}, bl0[2] = {l0, l1};
            uint32_t bh1[2] = {h2, h3}, bl1[2] = {l2, l3};
            mma_bf16(cacc[nb * 2], ahi, bh0);
            mma_bf16(cacc[nb * 2], ahi, bl0);
            mma_bf16(cacc[nb * 2], alo, bh0);
            mma_bf16(cacc[nb * 2 + 1], ahi, bh1);
            mma_bf16(cacc[nb * 2 + 1], ahi, bl1);
            mma_bf16(cacc[nb * 2 + 1], alo, bh1);
        }
    }

    const int h = bh & 15;
    __nv_bfloat16* chi0 = g_ctxhi + ((size_t)b * S_ + gi0) * DM_ + h * DK_;
    __nv_bfloat16* clo0 = g_ctxlo + ((size_t)b * S_ + gi0) * DM_ + h * DK_;
    __nv_bfloat16* chi1 = g_ctxhi + ((size_t)b * S_ + gi1) * DM_ + h * DK_;
    __nv_bfloat16* clo1 = g_ctxlo + ((size_t)b * S_ + gi1) * DM_ + h * DK_;
#pragma unroll
    for (int nf = 0; nf < 8; nf++) {
        int n = nf * 8 + c2;
        uint32_t hi0, lo0, hi1, lo1;
        split2(cacc[nf][0], cacc[nf][1], hi0, lo0);
        split2(cacc[nf][2], cacc[nf][3], hi1, lo1);
        if (v0ok) { *(uint32_t*)(chi0 + n) = hi0; *(uint32_t*)(clo0 + n) = lo0; }
        if (v1ok) { *(uint32_t*)(chi1 + n) = hi1; *(uint32_t*)(clo1 + n) = lo1; }
    }
}

// ---------------------------------------------------------------------------
extern "C" void kernel_launch(void* const* d_in, const int* in_sizes, int n_in,
                              void* d_out, int out_size)
{
    const float* x    = (const float*)d_in[0];
    const int*   mask = (const int*)  d_in[1];
    const float* wq   = (const float*)d_in[2];
    const float* bq   = (const float*)d_in[3];
    const float* wk   = (const float*)d_in[4];
    const float* bk   = (const float*)d_in[5];
    const float* wv   = (const float*)d_in[6];
    const float* bv   = (const float*)d_in[7];
    const float* wo   = (const float*)d_in[8];
    const float* bo   = (const float*)d_in[9];

    void *pxh, *pxl, *pwh, *pwl;
    void *pQh, *pQl, *pKh, *pKl, *pVh, *pVl, *pch, *pcl, *pAttnFb, *pOutFb;
    cudaGetSymbolAddress(&pxh, g_xhi);  cudaGetSymbolAddress(&pxl, g_xlo);
    cudaGetSymbolAddress(&pwh, g_whi);  cudaGetSymbolAddress(&pwl, g_wlo);
    cudaGetSymbolAddress(&pQh, g_Qhi);  cudaGetSymbolAddress(&pQl, g_Qlo);
    cudaGetSymbolAddress(&pKh, g_Khi);  cudaGetSymbolAddress(&pKl, g_Klo);
    cudaGetSymbolAddress(&pVh, g_Vhi);  cudaGetSymbolAddress(&pVl, g_Vlo);
    cudaGetSymbolAddress(&pch, g_ctxhi); cudaGetSymbolAddress(&pcl, g_ctxlo);
    cudaGetSymbolAddress(&pAttnFb, g_attn_fb);
    cudaGetSymbolAddress(&pOutFb, g_out_fb);

    __nv_bfloat16* xh = (__nv_bfloat16*)pxh;
    __nv_bfloat16* xl = (__nv_bfloat16*)pxl;
    __nv_bfloat16* wh = (__nv_bfloat16*)pwh;
    __nv_bfloat16* wl = (__nv_bfloat16*)pwl;

    float* outp;
    float* attnp;
    size_t osz = (size_t)out_size;
    if (osz >= OUT_N + ATTN_N) {
        outp  = (float*)d_out;
        attnp = (float*)d_out + OUT_N;
    } else if (osz == ATTN_N) {
        attnp = (float*)d_out;
        outp  = (float*)pOutFb;
    } else {
        outp  = (float*)d_out;
        attnp = (float*)pAttnFb;
    }

    cudaFuncSetAttribute(gemm_mma<0>, cudaFuncAttributeMaxDynamicSharedMemorySize, GEMM_SMEM);
    cudaFuncSetAttribute(gemm_mma<1>, cudaFuncAttributeMaxDynamicSharedMemorySize, GEMM_SMEM);
    cudaFuncSetAttribute(attn_fused, cudaFuncAttributeMaxDynamicSharedMemorySize, FA_SMEM);

    // Split inputs to bf16 hi/lo
    const int WN = DM_ * DM_;
    split_kernel<<<MROWS * DM_ / 2048, 256>>>(x,  xh, xl, MROWS * DM_);
    split_kernel<<<WN / 2048, 256>>>(wq, wh + 0 * (size_t)WN, wl + 0 * (size_t)WN, WN);
    split_kernel<<<WN / 2048, 256>>>(wk, wh + 1 * (size_t)WN, wl + 1 * (size_t)WN, WN);
    split_kernel<<<WN / 2048, 256>>>(wv, wh + 2 * (size_t)WN, wl + 2 * (size_t)WN, WN);
    split_kernel<<<WN / 2048, 256>>>(wo, wh + 3 * (size_t)WN, wl + 3 * (size_t)WN, WN);

    dim3 gProj(DM_ / 128, MROWS / 128);   // (8, 100)
    gemm_mma<0><<<gProj, 256, GEMM_SMEM>>>(xh, xl, wh + 0 * (size_t)WN, wl + 0 * (size_t)WN,
        bq, (__nv_bfloat16*)pQh, (__nv_bfloat16*)pQl, nullptr);
    gemm_mma<0><<<gProj, 256, GEMM_SMEM>>>(xh, xl, wh + 1 * (size_t)WN, wl + 1 * (size_t)WN,
        bk, (__nv_bfloat16*)pKh, (__nv_bfloat16*)pKl, nullptr);
    gemm_mma<0><<<gProj, 256, GEMM_SMEM>>>(xh, xl, wh + 2 * (size_t)WN, wl + 2 * (size_t)WN,
        bv, (__nv_bfloat16*)pVh, (__nv_bfloat16*)pVl, nullptr);

    dim3 gFA(2, BH_);                     // 128-row q tiles x (b*h)
    attn_fused<<<gFA, 256, FA_SMEM>>>(mask, attnp);

    gemm_mma<1><<<gProj, 256, GEMM_SMEM>>>((__nv_bfloat16*)pch, (__nv_bfloat16*)pcl,
        wh + 3 * (size_t)WN, wl + 3 * (size_t)WN, bo, nullptr, nullptr, outp);
}